// round 12
// baseline (speedup 1.0000x reference)
#include <cuda_runtime.h>
#include <math.h>

// Shapes
#define TT 16
#define NN 4096
#define II 4
#define HH 32
#define CC (NN * II)      // 16384 spline channels
#define NH (NN * HH)      // 131072 floats per z / k buffer

// GEMM tiling
#define BM 32
#define BK 64

// ---------------------------------------------------------------------------
// Device scratch (no allocations allowed)
// ---------------------------------------------------------------------------
__device__ float g_zs[TT * NH];        // z trajectory: zs[t][n][h]   (8 MB)
__device__ float g_k[3 * NH];          // k1,k2,k3 buffers            (1.5 MB)
__device__ float g_dx[3 * 15 * CC];    // dxdt at s=0,0.5,1 per step  (~3 MB)

// ---------------------------------------------------------------------------
// Kernel 1: natural cubic spline -> dX/dt samples at s = 0, 0.5, 1 per step
// One thread per channel c (c = n*4 + i). Thomas solve on the fixed
// tridiagonal [1 | 4..4 | 1] system with M[0] = M[T-1] = 0.
// ---------------------------------------------------------------------------
__global__ __launch_bounds__(256) void spline_kernel(const float* __restrict__ x,
                                                     float* __restrict__ gdx) {
    int c = blockIdx.x * blockDim.x + threadIdx.x;
    if (c >= CC) return;

    float y[16];
#pragma unroll
    for (int t = 0; t < 16; t++) y[t] = x[t * CC + c];

    // Thomas forward sweep for M[1..14] (a=1, diag=4, b=1)
    float cp[14], dp[14];
    float cprev = 0.f, dprev = 0.f;
#pragma unroll
    for (int i = 1; i <= 14; i++) {
        float rhs = 6.f * (y[i + 1] - 2.f * y[i] + y[i - 1]);
        float w = 1.f / (4.f - cprev);
        cprev = w;
        dprev = (rhs - dprev) * w;
        cp[i - 1] = cprev;
        dp[i - 1] = dprev;
    }
    float M[16];
    M[0] = 0.f;
    M[15] = 0.f;
    float Mn = 0.f;
#pragma unroll
    for (int i = 14; i >= 1; i--) {
        Mn = dp[i - 1] - cp[i - 1] * Mn;
        M[i] = Mn;
    }

#pragma unroll
    for (int i = 0; i < 15; i++) {
        float b = (y[i + 1] - y[i]) - (2.f * M[i] + M[i + 1]) * (1.f / 6.f);
        float cc2 = 0.5f * M[i];
        float dd = (M[i + 1] - M[i]) * (1.f / 6.f);
        gdx[(0 * 15 + i) * CC + c] = b;                          // s = 0
        gdx[(1 * 15 + i) * CC + c] = b + cc2 + 0.75f * dd;       // s = 0.5
        gdx[(2 * 15 + i) * CC + c] = b + 2.f * cc2 + 3.f * dd;   // s = 1
    }
}

// ---------------------------------------------------------------------------
// Kernel 2: z0 = x_path[0] @ W_enc + b_enc
// ---------------------------------------------------------------------------
__global__ __launch_bounds__(256) void z0_kernel(const float* __restrict__ x,
                                                 const float* __restrict__ We,
                                                 const float* __restrict__ be,
                                                 float* __restrict__ zs) {
    int idx = blockIdx.x * blockDim.x + threadIdx.x;   // 0 .. NH-1
    if (idx >= NH) return;
    int n = idx >> 5;
    int h = idx & 31;
    float s = be[h];
#pragma unroll
    for (int i = 0; i < 4; i++) s = fmaf(x[n * 4 + i], We[i * HH + h], s);
    zs[idx] = s;
}

// ---------------------------------------------------------------------------
// Kernel 3: fused RK4 stage.
//   zin = z + alpha * kp
//   zn  = adj @ zin                      (big GEMM, fused below)
//   h   = relu(zn @ W_gcn + zin @ W_time + b_gcn + b_time)
//   sens= h @ W_proj + b_proj  (N,H,I)
//   k   = einsum('nhi,ni->nh', sens, dx)
// If znext != null (stage 4): znext = z + (k1 + 2k2 + 2k3 + k)/6
// else: kout = k
//
// Grid: 128 CTAs (BM=32 rows each), 256 threads (8 warps x 4 rows, lane = col).
// ---------------------------------------------------------------------------
__global__ __launch_bounds__(256) void stage_kernel(
    const float* __restrict__ adj,
    const float* __restrict__ z,
    const float* __restrict__ kp,
    const float alpha,
    const float* __restrict__ dx,     // [NN][II]
    float* __restrict__ kout,
    const float* __restrict__ k1,
    const float* __restrict__ k2,
    const float* __restrict__ k3,
    float* __restrict__ znext,
    const float* __restrict__ Wg, const float* __restrict__ bg,
    const float* __restrict__ Wt, const float* __restrict__ bt,
    const float* __restrict__ Wp, const float* __restrict__ bp) {

    __shared__ float smem[8192];                 // 32 KB, reused by epilogue
    float* Asb = smem;                           // [2][BM][BK]
    float* Bsb = smem + 2 * BM * BK;             // [2][BK][HH]

    const int tid = threadIdx.x;
    const int lane = tid & 31;
    const int w = tid >> 5;
    const int mbase = blockIdx.x * BM;
    const int r0 = w << 2;                       // warp's first row in block

    // A-tile fill mapping: 512 float4 per chunk, 2 per thread
    const int aq0 = tid;
    const int ar0 = aq0 >> 4, ak0 = (aq0 & 15) << 2;
    const int aq1 = tid + 256;
    const int ar1 = aq1 >> 4, ak1 = (aq1 & 15) << 2;
    // B-tile fill mapping: 2048 floats per chunk, 8 per thread
    const int bc = tid & 31;
    const int bk0 = tid >> 5;

    const bool use_kp = (alpha != 0.f);

    float4 av0, av1;
    float bv[8];

    // ---- prologue: chunk 0 -> buffer 0 ----
    av0 = *reinterpret_cast<const float4*>(adj + (size_t)(mbase + ar0) * NN + ak0);
    av1 = *reinterpret_cast<const float4*>(adj + (size_t)(mbase + ar1) * NN + ak1);
#pragma unroll
    for (int j = 0; j < 8; j++) {
        int kr = bk0 + (j << 3);
        int gi = kr * HH + bc;
        float v = z[gi];
        if (use_kp) v = fmaf(alpha, kp[gi], v);
        bv[j] = v;
    }
    *reinterpret_cast<float4*>(Asb + ar0 * BK + ak0) = av0;
    *reinterpret_cast<float4*>(Asb + ar1 * BK + ak1) = av1;
#pragma unroll
    for (int j = 0; j < 8; j++) Bsb[(bk0 + (j << 3)) * HH + bc] = bv[j];
    __syncthreads();

    float acc0 = 0.f, acc1 = 0.f, acc2 = 0.f, acc3 = 0.f;
    int buf = 0;
    const int NC = NN / BK;   // 64 chunks

    for (int c = 0; c < NC; c++) {
        const bool more = (c + 1 < NC);
        const int knext = (c + 1) * BK;
        if (more) {
            av0 = *reinterpret_cast<const float4*>(adj + (size_t)(mbase + ar0) * NN + knext + ak0);
            av1 = *reinterpret_cast<const float4*>(adj + (size_t)(mbase + ar1) * NN + knext + ak1);
#pragma unroll
            for (int j = 0; j < 8; j++) {
                int kr = knext + bk0 + (j << 3);
                int gi = kr * HH + bc;
                float v = z[gi];
                if (use_kp) v = fmaf(alpha, kp[gi], v);
                bv[j] = v;
            }
        }
        const float* A = Asb + buf * (BM * BK) + r0 * BK;
        const float* B = Bsb + buf * (BK * HH) + lane;
#pragma unroll
        for (int kk = 0; kk < BK; kk += 4) {
            float4 a0 = *reinterpret_cast<const float4*>(A + 0 * BK + kk);
            float4 a1 = *reinterpret_cast<const float4*>(A + 1 * BK + kk);
            float4 a2 = *reinterpret_cast<const float4*>(A + 2 * BK + kk);
            float4 a3 = *reinterpret_cast<const float4*>(A + 3 * BK + kk);
            float b0 = B[(kk + 0) * HH];
            float b1 = B[(kk + 1) * HH];
            float b2 = B[(kk + 2) * HH];
            float b3 = B[(kk + 3) * HH];
            acc0 = fmaf(a0.x, b0, fmaf(a0.y, b1, fmaf(a0.z, b2, fmaf(a0.w, b3, acc0))));
            acc1 = fmaf(a1.x, b0, fmaf(a1.y, b1, fmaf(a1.z, b2, fmaf(a1.w, b3, acc1))));
            acc2 = fmaf(a2.x, b0, fmaf(a2.y, b1, fmaf(a2.z, b2, fmaf(a2.w, b3, acc2))));
            acc3 = fmaf(a3.x, b0, fmaf(a3.y, b1, fmaf(a3.z, b2, fmaf(a3.w, b3, acc3))));
        }
        if (more) {
            float* An = Asb + (buf ^ 1) * (BM * BK);
            float* Bn = Bsb + (buf ^ 1) * (BK * HH);
            *reinterpret_cast<float4*>(An + ar0 * BK + ak0) = av0;
            *reinterpret_cast<float4*>(An + ar1 * BK + ak1) = av1;
#pragma unroll
            for (int j = 0; j < 8; j++) Bn[(bk0 + (j << 3)) * HH + bc] = bv[j];
        }
        __syncthreads();
        buf ^= 1;
    }

    // ---- epilogue: reuse shared memory for the small weights ----
    float* Wg_s = smem;            // 1024
    float* Wt_s = smem + 1024;     // 1024
    float* Wp_s = smem + 2048;     // 4096  (Wp[j][h*4+i], row length 128)
    float* bgt_s = smem + 6144;    // 32
    float* bp_s = smem + 6176;     // 128 (16B aligned: 6176*4 % 16 == 0)

    for (int i = tid; i < 1024; i += 256) { Wg_s[i] = Wg[i]; Wt_s[i] = Wt[i]; }
    for (int i = tid; i < 4096; i += 256) Wp_s[i] = Wp[i];
    if (tid < 32) bgt_s[tid] = bg[tid] + bt[tid];
    if (tid < 128) bp_s[tid] = bp[tid];
    __syncthreads();

    const int grow0 = (mbase + r0) * HH;

    // zin rows for this warp (lane owns column = lane)
    float zi[4];
#pragma unroll
    for (int r = 0; r < 4; r++) {
        int g = grow0 + r * HH + lane;
        float v = z[g];
        if (use_kp) v = fmaf(alpha, kp[g], v);
        zi[r] = v;
    }

    // h = relu(zn @ Wg + zin @ Wt + bias), lane computes column `lane`
    float accv[4] = {acc0, acc1, acc2, acc3};
    float bgl = bgt_s[lane];
    float hv[4] = {bgl, bgl, bgl, bgl};
#pragma unroll
    for (int cc2 = 0; cc2 < 32; cc2++) {
        float wg = Wg_s[cc2 * HH + lane];
        float wt = Wt_s[cc2 * HH + lane];
#pragma unroll
        for (int r = 0; r < 4; r++) {
            hv[r] = fmaf(__shfl_sync(0xffffffffu, accv[r], cc2), wg, hv[r]);
            hv[r] = fmaf(__shfl_sync(0xffffffffu, zi[r], cc2), wt, hv[r]);
        }
    }
#pragma unroll
    for (int r = 0; r < 4; r++) hv[r] = fmaxf(hv[r], 0.f);

    // k[n, lane] = sum_i dx_i*bp[4*lane+i] + sum_j h_j * (Wp[j][4*lane..]·dx)
    float4 dxr[4];
#pragma unroll
    for (int r = 0; r < 4; r++)
        dxr[r] = *reinterpret_cast<const float4*>(dx + (mbase + r0 + r) * II);
    float4 bp4 = *reinterpret_cast<const float4*>(bp_s + lane * 4);
    float kv[4];
#pragma unroll
    for (int r = 0; r < 4; r++)
        kv[r] = bp4.x * dxr[r].x + bp4.y * dxr[r].y + bp4.z * dxr[r].z + bp4.w * dxr[r].w;
#pragma unroll
    for (int j = 0; j < 32; j++) {
        float4 wp = *reinterpret_cast<const float4*>(Wp_s + j * (HH * II) + lane * 4);
#pragma unroll
        for (int r = 0; r < 4; r++) {
            float t = wp.x * dxr[r].x + wp.y * dxr[r].y + wp.z * dxr[r].z + wp.w * dxr[r].w;
            kv[r] = fmaf(__shfl_sync(0xffffffffu, hv[r], j), t, kv[r]);
        }
    }

    if (znext == nullptr) {
#pragma unroll
        for (int r = 0; r < 4; r++) kout[grow0 + r * HH + lane] = kv[r];
    } else {
#pragma unroll
        for (int r = 0; r < 4; r++) {
            int g = grow0 + r * HH + lane;
            float zn = z[g] + (k1[g] + 2.f * k2[g] + 2.f * k3[g] + kv[r]) * (1.f / 6.f);
            znext[g] = zn;
        }
    }
}

// ---------------------------------------------------------------------------
// Kernel 4: decoder over all (T, N) rows
//   out = sigmoid(relu(z @ W_d1 + b_d1) @ W_d2 + b_d2)
// ---------------------------------------------------------------------------
__global__ __launch_bounds__(256) void decode_kernel(const float* __restrict__ zs,
                                                     const float* __restrict__ W1,
                                                     const float* __restrict__ b1,
                                                     const float* __restrict__ W2,
                                                     const float* __restrict__ b2,
                                                     float* __restrict__ out) {
    __shared__ float sW1[HH * 16];
    __shared__ float sb1[16];
    __shared__ float sW2[16];
    __shared__ float sb2;
    int tid = threadIdx.x;
    for (int i = tid; i < HH * 16; i += 256) sW1[i] = W1[i];
    if (tid < 16) { sb1[tid] = b1[tid]; sW2[tid] = W2[tid]; }
    if (tid == 0) sb2 = b2[0];
    __syncthreads();

    int r = blockIdx.x * blockDim.x + tid;    // 0 .. TT*NN-1
    if (r >= TT * NN) return;
    const float* zrow = zs + (size_t)r * HH;
    float zv[HH];
#pragma unroll
    for (int i = 0; i < HH; i += 4) {
        float4 v = *reinterpret_cast<const float4*>(zrow + i);
        zv[i] = v.x; zv[i + 1] = v.y; zv[i + 2] = v.z; zv[i + 3] = v.w;
    }
    float o = sb2;
#pragma unroll
    for (int j = 0; j < 16; j++) {
        float hd = sb1[j];
#pragma unroll
        for (int c2 = 0; c2 < HH; c2++) hd = fmaf(zv[c2], sW1[c2 * 16 + j], hd);
        hd = fmaxf(hd, 0.f);
        o = fmaf(hd, sW2[j], o);
    }
    out[r] = 1.f / (1.f + expf(-o));
}

// ---------------------------------------------------------------------------
// Host launcher (graph-capturable: kernel launches only)
// ---------------------------------------------------------------------------
extern "C" void kernel_launch(void* const* d_in, const int* in_sizes, int n_in,
                              void* d_out, int out_size) {
    const float* x   = (const float*)d_in[0];
    const float* adj = (const float*)d_in[1];
    const float* We  = (const float*)d_in[2];
    const float* be  = (const float*)d_in[3];
    const float* Wg  = (const float*)d_in[4];
    const float* bg  = (const float*)d_in[5];
    const float* Wt  = (const float*)d_in[6];
    const float* bt  = (const float*)d_in[7];
    const float* Wp  = (const float*)d_in[8];
    const float* bp  = (const float*)d_in[9];
    const float* W1  = (const float*)d_in[10];
    const float* b1  = (const float*)d_in[11];
    const float* W2  = (const float*)d_in[12];
    const float* b2  = (const float*)d_in[13];
    float* out = (float*)d_out;

    float *zs, *kb, *dxb;
    cudaGetSymbolAddress((void**)&zs, g_zs);
    cudaGetSymbolAddress((void**)&kb, g_k);
    cudaGetSymbolAddress((void**)&dxb, g_dx);

    spline_kernel<<<CC / 256, 256>>>(x, dxb);
    z0_kernel<<<NH / 256, 256>>>(x, We, be, zs);

    for (int t = 0; t < 15; t++) {
        const float* zcur = zs + (size_t)t * NH;
        float* zn = zs + (size_t)(t + 1) * NH;
        float* k1 = kb;
        float* k2 = kb + NH;
        float* k3 = kb + 2 * NH;
        const float* dx0 = dxb + (0 * 15 + t) * CC;
        const float* dxh = dxb + (1 * 15 + t) * CC;
        const float* dx1 = dxb + (2 * 15 + t) * CC;

        stage_kernel<<<NN / BM, 256>>>(adj, zcur, zcur, 0.0f, dx0, k1,
                                       nullptr, nullptr, nullptr, nullptr,
                                       Wg, bg, Wt, bt, Wp, bp);
        stage_kernel<<<NN / BM, 256>>>(adj, zcur, k1, 0.5f, dxh, k2,
                                       nullptr, nullptr, nullptr, nullptr,
                                       Wg, bg, Wt, bt, Wp, bp);
        stage_kernel<<<NN / BM, 256>>>(adj, zcur, k2, 0.5f, dxh, k3,
                                       nullptr, nullptr, nullptr, nullptr,
                                       Wg, bg, Wt, bt, Wp, bp);
        stage_kernel<<<NN / BM, 256>>>(adj, zcur, k3, 1.0f, dx1, k1 /*unused*/,
                                       k1, k2, k3, zn,
                                       Wg, bg, Wt, bt, Wp, bp);
    }

    decode_kernel<<<(TT * NN) / 256, 256>>>(zs, W1, b1, W2, b2, out);
}

// round 13
// speedup vs baseline: 1.0002x; 1.0002x over previous
#include <cuda_runtime.h>
#include <math.h>

// Shapes
#define TT 16
#define NN 4096
#define II 4
#define HH 32
#define CC (NN * II)      // 16384 spline channels
#define NH (NN * HH)      // 131072 floats per z / k buffer

// GEMM tiling
#define BM 32
#define BK 64

// ---------------------------------------------------------------------------
// Device scratch (no allocations allowed)
// ---------------------------------------------------------------------------
__device__ float g_zs[TT * NH];        // z trajectory: zs[t][n][h]   (8 MB)
__device__ float g_k[3 * NH];          // k1,k2,k3 buffers            (1.5 MB)
__device__ float g_dx[3 * 15 * CC];    // dxdt at s=0,0.5,1 per step  (~3 MB)

// ---------------------------------------------------------------------------
// Kernel 1: natural cubic spline -> dX/dt samples at s = 0, 0.5, 1 per step
// One thread per channel c (c = n*4 + i). Thomas solve on the fixed
// tridiagonal [1 | 4..4 | 1] system with M[0] = M[T-1] = 0.
// ---------------------------------------------------------------------------
__global__ __launch_bounds__(256) void spline_kernel(const float* __restrict__ x,
                                                     float* __restrict__ gdx) {
    int c = blockIdx.x * blockDim.x + threadIdx.x;
    if (c >= CC) return;

    float y[16];
#pragma unroll
    for (int t = 0; t < 16; t++) y[t] = x[t * CC + c];

    // Thomas forward sweep for M[1..14] (a=1, diag=4, b=1)
    float cp[14], dp[14];
    float cprev = 0.f, dprev = 0.f;
#pragma unroll
    for (int i = 1; i <= 14; i++) {
        float rhs = 6.f * (y[i + 1] - 2.f * y[i] + y[i - 1]);
        float w = 1.f / (4.f - cprev);
        cprev = w;
        dprev = (rhs - dprev) * w;
        cp[i - 1] = cprev;
        dp[i - 1] = dprev;
    }
    float M[16];
    M[0] = 0.f;
    M[15] = 0.f;
    float Mn = 0.f;
#pragma unroll
    for (int i = 14; i >= 1; i--) {
        Mn = dp[i - 1] - cp[i - 1] * Mn;
        M[i] = Mn;
    }

#pragma unroll
    for (int i = 0; i < 15; i++) {
        float b = (y[i + 1] - y[i]) - (2.f * M[i] + M[i + 1]) * (1.f / 6.f);
        float cc2 = 0.5f * M[i];
        float dd = (M[i + 1] - M[i]) * (1.f / 6.f);
        gdx[(0 * 15 + i) * CC + c] = b;                          // s = 0
        gdx[(1 * 15 + i) * CC + c] = b + cc2 + 0.75f * dd;       // s = 0.5
        gdx[(2 * 15 + i) * CC + c] = b + 2.f * cc2 + 3.f * dd;   // s = 1
    }
}

// ---------------------------------------------------------------------------
// Kernel 2: z0 = x_path[0] @ W_enc + b_enc
// ---------------------------------------------------------------------------
__global__ __launch_bounds__(256) void z0_kernel(const float* __restrict__ x,
                                                 const float* __restrict__ We,
                                                 const float* __restrict__ be,
                                                 float* __restrict__ zs) {
    int idx = blockIdx.x * blockDim.x + threadIdx.x;   // 0 .. NH-1
    if (idx >= NH) return;
    int n = idx >> 5;
    int h = idx & 31;
    float s = be[h];
#pragma unroll
    for (int i = 0; i < 4; i++) s = fmaf(x[n * 4 + i], We[i * HH + h], s);
    zs[idx] = s;
}

// ---------------------------------------------------------------------------
// Kernel 3: fused RK4 stage.
//   zin = z + alpha * kp
//   zn  = adj @ zin                      (big GEMM, fused below)
//   h   = relu(zn @ W_gcn + zin @ W_time + b_gcn + b_time)
//   sens= h @ W_proj + b_proj  (N,H,I)
//   k   = einsum('nhi,ni->nh', sens, dx)
// If znext != null (stage 4): znext = z + (k1 + 2k2 + 2k3 + k)/6
// else: kout = k
//
// Grid: 128 CTAs (BM=32 rows each), 256 threads (8 warps x 4 rows, lane = col).
// ---------------------------------------------------------------------------
__global__ __launch_bounds__(256) void stage_kernel(
    const float* __restrict__ adj,
    const float* __restrict__ z,
    const float* __restrict__ kp,
    const float alpha,
    const float* __restrict__ dx,     // [NN][II]
    float* __restrict__ kout,
    const float* __restrict__ k1,
    const float* __restrict__ k2,
    const float* __restrict__ k3,
    float* __restrict__ znext,
    const float* __restrict__ Wg, const float* __restrict__ bg,
    const float* __restrict__ Wt, const float* __restrict__ bt,
    const float* __restrict__ Wp, const float* __restrict__ bp) {

    __shared__ float smem[8192];                 // 32 KB, reused by epilogue
    float* Asb = smem;                           // [2][BM][BK]
    float* Bsb = smem + 2 * BM * BK;             // [2][BK][HH]

    const int tid = threadIdx.x;
    const int lane = tid & 31;
    const int w = tid >> 5;
    const int mbase = blockIdx.x * BM;
    const int r0 = w << 2;                       // warp's first row in block

    // A-tile fill mapping: 512 float4 per chunk, 2 per thread
    const int aq0 = tid;
    const int ar0 = aq0 >> 4, ak0 = (aq0 & 15) << 2;
    const int aq1 = tid + 256;
    const int ar1 = aq1 >> 4, ak1 = (aq1 & 15) << 2;
    // B-tile fill mapping: 2048 floats per chunk, 8 per thread
    const int bc = tid & 31;
    const int bk0 = tid >> 5;

    const bool use_kp = (alpha != 0.f);

    float4 av0, av1;
    float bv[8];

    // ---- prologue: chunk 0 -> buffer 0 ----
    av0 = *reinterpret_cast<const float4*>(adj + (size_t)(mbase + ar0) * NN + ak0);
    av1 = *reinterpret_cast<const float4*>(adj + (size_t)(mbase + ar1) * NN + ak1);
#pragma unroll
    for (int j = 0; j < 8; j++) {
        int kr = bk0 + (j << 3);
        int gi = kr * HH + bc;
        float v = z[gi];
        if (use_kp) v = fmaf(alpha, kp[gi], v);
        bv[j] = v;
    }
    *reinterpret_cast<float4*>(Asb + ar0 * BK + ak0) = av0;
    *reinterpret_cast<float4*>(Asb + ar1 * BK + ak1) = av1;
#pragma unroll
    for (int j = 0; j < 8; j++) Bsb[(bk0 + (j << 3)) * HH + bc] = bv[j];
    __syncthreads();

    float acc0 = 0.f, acc1 = 0.f, acc2 = 0.f, acc3 = 0.f;
    int buf = 0;
    const int NC = NN / BK;   // 64 chunks

    for (int c = 0; c < NC; c++) {
        const bool more = (c + 1 < NC);
        const int knext = (c + 1) * BK;
        if (more) {
            av0 = *reinterpret_cast<const float4*>(adj + (size_t)(mbase + ar0) * NN + knext + ak0);
            av1 = *reinterpret_cast<const float4*>(adj + (size_t)(mbase + ar1) * NN + knext + ak1);
#pragma unroll
            for (int j = 0; j < 8; j++) {
                int kr = knext + bk0 + (j << 3);
                int gi = kr * HH + bc;
                float v = z[gi];
                if (use_kp) v = fmaf(alpha, kp[gi], v);
                bv[j] = v;
            }
        }
        const float* A = Asb + buf * (BM * BK) + r0 * BK;
        const float* B = Bsb + buf * (BK * HH) + lane;
#pragma unroll
        for (int kk = 0; kk < BK; kk += 4) {
            float4 a0 = *reinterpret_cast<const float4*>(A + 0 * BK + kk);
            float4 a1 = *reinterpret_cast<const float4*>(A + 1 * BK + kk);
            float4 a2 = *reinterpret_cast<const float4*>(A + 2 * BK + kk);
            float4 a3 = *reinterpret_cast<const float4*>(A + 3 * BK + kk);
            float b0 = B[(kk + 0) * HH];
            float b1 = B[(kk + 1) * HH];
            float b2 = B[(kk + 2) * HH];
            float b3 = B[(kk + 3) * HH];
            acc0 = fmaf(a0.x, b0, fmaf(a0.y, b1, fmaf(a0.z, b2, fmaf(a0.w, b3, acc0))));
            acc1 = fmaf(a1.x, b0, fmaf(a1.y, b1, fmaf(a1.z, b2, fmaf(a1.w, b3, acc1))));
            acc2 = fmaf(a2.x, b0, fmaf(a2.y, b1, fmaf(a2.z, b2, fmaf(a2.w, b3, acc2))));
            acc3 = fmaf(a3.x, b0, fmaf(a3.y, b1, fmaf(a3.z, b2, fmaf(a3.w, b3, acc3))));
        }
        if (more) {
            float* An = Asb + (buf ^ 1) * (BM * BK);
            float* Bn = Bsb + (buf ^ 1) * (BK * HH);
            *reinterpret_cast<float4*>(An + ar0 * BK + ak0) = av0;
            *reinterpret_cast<float4*>(An + ar1 * BK + ak1) = av1;
#pragma unroll
            for (int j = 0; j < 8; j++) Bn[(bk0 + (j << 3)) * HH + bc] = bv[j];
        }
        __syncthreads();
        buf ^= 1;
    }

    // ---- epilogue: reuse shared memory for the small weights ----
    float* Wg_s = smem;            // 1024
    float* Wt_s = smem + 1024;     // 1024
    float* Wp_s = smem + 2048;     // 4096  (Wp[j][h*4+i], row length 128)
    float* bgt_s = smem + 6144;    // 32
    float* bp_s = smem + 6176;     // 128 (16B aligned: 6176*4 % 16 == 0)

    for (int i = tid; i < 1024; i += 256) { Wg_s[i] = Wg[i]; Wt_s[i] = Wt[i]; }
    for (int i = tid; i < 4096; i += 256) Wp_s[i] = Wp[i];
    if (tid < 32) bgt_s[tid] = bg[tid] + bt[tid];
    if (tid < 128) bp_s[tid] = bp[tid];
    __syncthreads();

    const int grow0 = (mbase + r0) * HH;

    // zin rows for this warp (lane owns column = lane)
    float zi[4];
#pragma unroll
    for (int r = 0; r < 4; r++) {
        int g = grow0 + r * HH + lane;
        float v = z[g];
        if (use_kp) v = fmaf(alpha, kp[g], v);
        zi[r] = v;
    }

    // h = relu(zn @ Wg + zin @ Wt + bias), lane computes column `lane`
    float accv[4] = {acc0, acc1, acc2, acc3};
    float bgl = bgt_s[lane];
    float hv[4] = {bgl, bgl, bgl, bgl};
#pragma unroll
    for (int cc2 = 0; cc2 < 32; cc2++) {
        float wg = Wg_s[cc2 * HH + lane];
        float wt = Wt_s[cc2 * HH + lane];
#pragma unroll
        for (int r = 0; r < 4; r++) {
            hv[r] = fmaf(__shfl_sync(0xffffffffu, accv[r], cc2), wg, hv[r]);
            hv[r] = fmaf(__shfl_sync(0xffffffffu, zi[r], cc2), wt, hv[r]);
        }
    }
#pragma unroll
    for (int r = 0; r < 4; r++) hv[r] = fmaxf(hv[r], 0.f);

    // k[n, lane] = sum_i dx_i*bp[4*lane+i] + sum_j h_j * (Wp[j][4*lane..]·dx)
    float4 dxr[4];
#pragma unroll
    for (int r = 0; r < 4; r++)
        dxr[r] = *reinterpret_cast<const float4*>(dx + (mbase + r0 + r) * II);
    float4 bp4 = *reinterpret_cast<const float4*>(bp_s + lane * 4);
    float kv[4];
#pragma unroll
    for (int r = 0; r < 4; r++)
        kv[r] = bp4.x * dxr[r].x + bp4.y * dxr[r].y + bp4.z * dxr[r].z + bp4.w * dxr[r].w;
#pragma unroll
    for (int j = 0; j < 32; j++) {
        float4 wp = *reinterpret_cast<const float4*>(Wp_s + j * (HH * II) + lane * 4);
#pragma unroll
        for (int r = 0; r < 4; r++) {
            float t = wp.x * dxr[r].x + wp.y * dxr[r].y + wp.z * dxr[r].z + wp.w * dxr[r].w;
            kv[r] = fmaf(__shfl_sync(0xffffffffu, hv[r], j), t, kv[r]);
        }
    }

    if (znext == nullptr) {
#pragma unroll
        for (int r = 0; r < 4; r++) kout[grow0 + r * HH + lane] = kv[r];
    } else {
#pragma unroll
        for (int r = 0; r < 4; r++) {
            int g = grow0 + r * HH + lane;
            float zn = z[g] + (k1[g] + 2.f * k2[g] + 2.f * k3[g] + kv[r]) * (1.f / 6.f);
            znext[g] = zn;
        }
    }
}

// ---------------------------------------------------------------------------
// Kernel 4: decoder over all (T, N) rows
//   out = sigmoid(relu(z @ W_d1 + b_d1) @ W_d2 + b_d2)
// ---------------------------------------------------------------------------
__global__ __launch_bounds__(256) void decode_kernel(const float* __restrict__ zs,
                                                     const float* __restrict__ W1,
                                                     const float* __restrict__ b1,
                                                     const float* __restrict__ W2,
                                                     const float* __restrict__ b2,
                                                     float* __restrict__ out) {
    __shared__ float sW1[HH * 16];
    __shared__ float sb1[16];
    __shared__ float sW2[16];
    __shared__ float sb2;
    int tid = threadIdx.x;
    for (int i = tid; i < HH * 16; i += 256) sW1[i] = W1[i];
    if (tid < 16) { sb1[tid] = b1[tid]; sW2[tid] = W2[tid]; }
    if (tid == 0) sb2 = b2[0];
    __syncthreads();

    int r = blockIdx.x * blockDim.x + tid;    // 0 .. TT*NN-1
    if (r >= TT * NN) return;
    const float* zrow = zs + (size_t)r * HH;
    float zv[HH];
#pragma unroll
    for (int i = 0; i < HH; i += 4) {
        float4 v = *reinterpret_cast<const float4*>(zrow + i);
        zv[i] = v.x; zv[i + 1] = v.y; zv[i + 2] = v.z; zv[i + 3] = v.w;
    }
    float o = sb2;
#pragma unroll
    for (int j = 0; j < 16; j++) {
        float hd = sb1[j];
#pragma unroll
        for (int c2 = 0; c2 < HH; c2++) hd = fmaf(zv[c2], sW1[c2 * 16 + j], hd);
        hd = fmaxf(hd, 0.f);
        o = fmaf(hd, sW2[j], o);
    }
    out[r] = 1.f / (1.f + expf(-o));
}

// ---------------------------------------------------------------------------
// Host launcher (graph-capturable: kernel launches only)
// ---------------------------------------------------------------------------
extern "C" void kernel_launch(void* const* d_in, const int* in_sizes, int n_in,
                              void* d_out, int out_size) {
    const float* x   = (const float*)d_in[0];
    const float* adj = (const float*)d_in[1];
    const float* We  = (const float*)d_in[2];
    const float* be  = (const float*)d_in[3];
    const float* Wg  = (const float*)d_in[4];
    const float* bg  = (const float*)d_in[5];
    const float* Wt  = (const float*)d_in[6];
    const float* bt  = (const float*)d_in[7];
    const float* Wp  = (const float*)d_in[8];
    const float* bp  = (const float*)d_in[9];
    const float* W1  = (const float*)d_in[10];
    const float* b1  = (const float*)d_in[11];
    const float* W2  = (const float*)d_in[12];
    const float* b2  = (const float*)d_in[13];
    float* out = (float*)d_out;

    float *zs, *kb, *dxb;
    cudaGetSymbolAddress((void**)&zs, g_zs);
    cudaGetSymbolAddress((void**)&kb, g_k);
    cudaGetSymbolAddress((void**)&dxb, g_dx);

    spline_kernel<<<CC / 256, 256>>>(x, dxb);
    z0_kernel<<<NH / 256, 256>>>(x, We, be, zs);

    for (int t = 0; t < 15; t++) {
        const float* zcur = zs + (size_t)t * NH;
        float* zn = zs + (size_t)(t + 1) * NH;
        float* k1 = kb;
        float* k2 = kb + NH;
        float* k3 = kb + 2 * NH;
        const float* dx0 = dxb + (0 * 15 + t) * CC;
        const float* dxh = dxb + (1 * 15 + t) * CC;
        const float* dx1 = dxb + (2 * 15 + t) * CC;

        stage_kernel<<<NN / BM, 256>>>(adj, zcur, zcur, 0.0f, dx0, k1,
                                       nullptr, nullptr, nullptr, nullptr,
                                       Wg, bg, Wt, bt, Wp, bp);
        stage_kernel<<<NN / BM, 256>>>(adj, zcur, k1, 0.5f, dxh, k2,
                                       nullptr, nullptr, nullptr, nullptr,
                                       Wg, bg, Wt, bt, Wp, bp);
        stage_kernel<<<NN / BM, 256>>>(adj, zcur, k2, 0.5f, dxh, k3,
                                       nullptr, nullptr, nullptr, nullptr,
                                       Wg, bg, Wt, bt, Wp, bp);
        stage_kernel<<<NN / BM, 256>>>(adj, zcur, k3, 1.0f, dx1, k1 /*unused*/,
                                       k1, k2, k3, zn,
                                       Wg, bg, Wt, bt, Wp, bp);
    }

    decode_kernel<<<(TT * NN) / 256, 256>>>(zs, W1, b1, W2, b2, out);
}

// round 14
// speedup vs baseline: 2.6575x; 2.6570x over previous
#include <cuda_runtime.h>
#include <cuda_bf16.h>
#include <math.h>

// Shapes
#define TT 16
#define NN 4096
#define II 4
#define HH 32
#define CC (NN * II)      // 16384 spline channels
#define NH (NN * HH)      // 131072 floats per z / k buffer
#define BM 32             // rows per CTA in the big GEMM

// ---------------------------------------------------------------------------
// Device scratch (no allocations allowed)
// ---------------------------------------------------------------------------
__device__ float g_zs[TT * NH];          // z trajectory (8 MB)
__device__ float g_k[3 * NH];            // k1,k2,k3
__device__ float g_dx[3 * 15 * CC];      // dxdt samples
// adj split into bf16 hi/lo, packed per 4 columns: [h0,h1,h2,h3,l0,l1,l2,l3]
// adjP[row][pack] : 4096 rows x 1024 packs x 16B = 64 MB
__device__ uint4 g_adjP[NN * 1024];
// zin^T in same packed format: [h-channel(32)][pack(1024)], double-buffered
__device__ uint4 g_zT[2][HH * 1024];

// ---------------------------------------------------------------------------
// helpers
// ---------------------------------------------------------------------------
__device__ __forceinline__ void bf16split(float v, unsigned short& h, unsigned short& l) {
    __nv_bfloat16 bh = __float2bfloat16_rn(v);
    float r = v - __bfloat162float(bh);
    __nv_bfloat16 bl = __float2bfloat16_rn(r);
    h = __bfloat16_as_ushort(bh);
    l = __bfloat16_as_ushort(bl);
}

__device__ __forceinline__ void mma16816(float* c,
                                         unsigned a0, unsigned a1, unsigned a2, unsigned a3,
                                         unsigned b0, unsigned b1) {
    asm volatile(
        "mma.sync.aligned.m16n8k16.row.col.f32.bf16.bf16.f32 "
        "{%0,%1,%2,%3},{%4,%5,%6,%7},{%8,%9},{%0,%1,%2,%3};\n"
        : "+f"(c[0]), "+f"(c[1]), "+f"(c[2]), "+f"(c[3])
        : "r"(a0), "r"(a1), "r"(a2), "r"(a3), "r"(b0), "r"(b1));
}

__device__ __forceinline__ void mma_iter(float (&acc)[4][4],
                                         const uint4& A0v, const uint4& A1v,
                                         const uint4& B0v, const uint4& B1v,
                                         const uint4& B2v, const uint4& B3v) {
    // hi * hi
    mma16816(acc[0], A0v.x, A1v.x, A0v.y, A1v.y, B0v.x, B0v.y);
    mma16816(acc[1], A0v.x, A1v.x, A0v.y, A1v.y, B1v.x, B1v.y);
    mma16816(acc[2], A0v.x, A1v.x, A0v.y, A1v.y, B2v.x, B2v.y);
    mma16816(acc[3], A0v.x, A1v.x, A0v.y, A1v.y, B3v.x, B3v.y);
    // hi * lo
    mma16816(acc[0], A0v.x, A1v.x, A0v.y, A1v.y, B0v.z, B0v.w);
    mma16816(acc[1], A0v.x, A1v.x, A0v.y, A1v.y, B1v.z, B1v.w);
    mma16816(acc[2], A0v.x, A1v.x, A0v.y, A1v.y, B2v.z, B2v.w);
    mma16816(acc[3], A0v.x, A1v.x, A0v.y, A1v.y, B3v.z, B3v.w);
    // lo * hi
    mma16816(acc[0], A0v.z, A1v.z, A0v.w, A1v.w, B0v.x, B0v.y);
    mma16816(acc[1], A0v.z, A1v.z, A0v.w, A1v.w, B1v.x, B1v.y);
    mma16816(acc[2], A0v.z, A1v.z, A0v.w, A1v.w, B2v.x, B2v.y);
    mma16816(acc[3], A0v.z, A1v.z, A0v.w, A1v.w, B3v.x, B3v.y);
}

// ---------------------------------------------------------------------------
// Kernel 0: convert adj (fp32) to packed bf16 hi/lo
// ---------------------------------------------------------------------------
__global__ __launch_bounds__(256) void conv_adj(const float* __restrict__ adj,
                                                uint4* __restrict__ out) {
    int gi = blockIdx.x * 256 + threadIdx.x;   // row*1024 + pack
    float4 v = reinterpret_cast<const float4*>(adj)[gi];
    unsigned short h0, h1, h2, h3, l0, l1, l2, l3;
    bf16split(v.x, h0, l0);
    bf16split(v.y, h1, l1);
    bf16split(v.z, h2, l2);
    bf16split(v.w, h3, l3);
    uint4 o;
    o.x = (unsigned)h0 | ((unsigned)h1 << 16);
    o.y = (unsigned)h2 | ((unsigned)h3 << 16);
    o.z = (unsigned)l0 | ((unsigned)l1 << 16);
    o.w = (unsigned)l2 | ((unsigned)l3 << 16);
    out[gi] = o;
}

// ---------------------------------------------------------------------------
// Kernel 1: natural cubic spline -> dX/dt samples at s = 0, 0.5, 1 per step
// ---------------------------------------------------------------------------
__global__ __launch_bounds__(256) void spline_kernel(const float* __restrict__ x,
                                                     float* __restrict__ gdx) {
    int c = blockIdx.x * blockDim.x + threadIdx.x;
    if (c >= CC) return;

    float y[16];
#pragma unroll
    for (int t = 0; t < 16; t++) y[t] = x[t * CC + c];

    float cp[14], dp[14];
    float cprev = 0.f, dprev = 0.f;
#pragma unroll
    for (int i = 1; i <= 14; i++) {
        float rhs = 6.f * (y[i + 1] - 2.f * y[i] + y[i - 1]);
        float w = 1.f / (4.f - cprev);
        cprev = w;
        dprev = (rhs - dprev) * w;
        cp[i - 1] = cprev;
        dp[i - 1] = dprev;
    }
    float M[16];
    M[0] = 0.f;
    M[15] = 0.f;
    float Mn = 0.f;
#pragma unroll
    for (int i = 14; i >= 1; i--) {
        Mn = dp[i - 1] - cp[i - 1] * Mn;
        M[i] = Mn;
    }

#pragma unroll
    for (int i = 0; i < 15; i++) {
        float b = (y[i + 1] - y[i]) - (2.f * M[i] + M[i + 1]) * (1.f / 6.f);
        float cc2 = 0.5f * M[i];
        float dd = (M[i + 1] - M[i]) * (1.f / 6.f);
        gdx[(0 * 15 + i) * CC + c] = b;
        gdx[(1 * 15 + i) * CC + c] = b + cc2 + 0.75f * dd;
        gdx[(2 * 15 + i) * CC + c] = b + 2.f * cc2 + 3.f * dd;
    }
}

// ---------------------------------------------------------------------------
// Kernel 2: z0 = x_path[0] @ W_enc + b_enc; also write zin^T packed bf16
// ---------------------------------------------------------------------------
__global__ __launch_bounds__(256) void z0_kernel(const float* __restrict__ x,
                                                 const float* __restrict__ We,
                                                 const float* __restrict__ be,
                                                 float* __restrict__ zs,
                                                 unsigned short* __restrict__ zt) {
    int idx = blockIdx.x * blockDim.x + threadIdx.x;   // 0 .. NH-1
    if (idx >= NH) return;
    int n = idx >> 5;
    int h = idx & 31;
    float s = be[h];
#pragma unroll
    for (int i = 0; i < 4; i++) s = fmaf(x[n * 4 + i], We[i * HH + h], s);
    zs[idx] = s;
    unsigned short hh, ll;
    bf16split(s, hh, ll);
    int base = h * 8192 + (n >> 2) * 8 + (n & 3);
    zt[base] = hh;
    zt[base + 4] = ll;
}

// ---------------------------------------------------------------------------
// Kernel 3: fused RK4 stage with tensor-core GEMM.
//   zn = adj @ zin  via split-bf16 mma (zin read as packed zT from zTr)
//   h  = relu(zn @ Wg + zin @ Wt + b);  sens = h @ Wp + bp;  k = sens . dx
//   stage 1-3: kout = k;  next zin = z + beta*k  -> written packed to zTw
//   stage 4:   znext = z + (k1+2k2+2k3+k)/6;     next zin = znext -> zTw
// Grid: 128 CTAs, 256 threads = 8 warps: warp w -> m-tile (w&1), k-phase (w>>1)
// ---------------------------------------------------------------------------
__global__ __launch_bounds__(256) void stage_kernel(
    const uint4* __restrict__ adjP,
    const uint4* __restrict__ zTr,
    uint4* __restrict__ zTw,
    const float* __restrict__ z,
    const float* __restrict__ kp,
    const float alpha,                 // zin = z + alpha*kp (epilogue only)
    const float beta,                  // next zin = z + beta*k (stages 1-3)
    const float* __restrict__ dx,
    float* __restrict__ kout,
    const float* __restrict__ k1,
    const float* __restrict__ k2,
    const float* __restrict__ k3,
    float* __restrict__ znext,
    const float* __restrict__ Wg, const float* __restrict__ bg,
    const float* __restrict__ Wt, const float* __restrict__ bt,
    const float* __restrict__ Wp, const float* __restrict__ bp) {

    __shared__ __align__(16) float psum_s[4 * 1056];   // per-k-phase partials (pitch 33)
    __shared__ __align__(16) float zn_s[1056];         // reduced zn (pitch 33)
    __shared__ __align__(16) float w_s[6304];          // Wg|Wt|Wp|bgt|bp

    const int tid = threadIdx.x;
    const int lane = tid & 31;
    const int w = tid >> 5;
    const int mbase = blockIdx.x * BM;
    const int g = lane >> 2, tq = lane & 3;
    const int mt = w & 1, kph = w >> 1;

    // ---- tensor-core mainloop: no smem, fragments straight from L2 ----
    const uint4* Ar0 = adjP + (size_t)(mbase + mt * 16 + g) * 1024;
    const uint4* Ar1 = Ar0 + 8 * 1024;
    const uint4* B0 = zTr + (size_t)(g) * 1024;
    const uint4* B1 = zTr + (size_t)(8 + g) * 1024;
    const uint4* B2 = zTr + (size_t)(16 + g) * 1024;
    const uint4* B3 = zTr + (size_t)(24 + g) * 1024;

    float acc[4][4];
#pragma unroll
    for (int i = 0; i < 4; i++)
#pragma unroll
        for (int j = 0; j < 4; j++) acc[i][j] = 0.f;

    int p = kph * 4 + tq;
    uint4 A0v = Ar0[p], A1v = Ar1[p];
    uint4 B0v = B0[p], B1v = B1[p], B2v = B2[p], B3v = B3[p];

#pragma unroll 2
    for (int c = 0; c < 63; c++) {
        const int pn = p + 16;
        uint4 nA0 = Ar0[pn], nA1 = Ar1[pn];
        uint4 nB0 = B0[pn], nB1 = B1[pn], nB2 = B2[pn], nB3 = B3[pn];
        mma_iter(acc, A0v, A1v, B0v, B1v, B2v, B3v);
        A0v = nA0; A1v = nA1;
        B0v = nB0; B1v = nB1; B2v = nB2; B3v = nB3;
        p = pn;
    }
    mma_iter(acc, A0v, A1v, B0v, B1v, B2v, B3v);

    // ---- store per-phase partials ----
    {
        const int kOff = kph * 1056;
        const int row = mt * 16 + g;
#pragma unroll
        for (int nt = 0; nt < 4; nt++) {
            const int cb = nt * 8 + 2 * tq;
            psum_s[kOff + row * 33 + cb]       = acc[nt][0];
            psum_s[kOff + row * 33 + cb + 1]   = acc[nt][1];
            psum_s[kOff + (row + 8) * 33 + cb]     = acc[nt][2];
            psum_s[kOff + (row + 8) * 33 + cb + 1] = acc[nt][3];
        }
    }
    __syncthreads();

    // ---- reduce 4 k-phases -> zn_s; load epilogue weights ----
    {
        const int col = tid & 31, r4 = tid >> 5;
#pragma unroll
        for (int j = 0; j < 4; j++) {
            const int row = r4 + j * 8;
            const int o = row * 33 + col;
            zn_s[o] = psum_s[o] + psum_s[1056 + o] + psum_s[2112 + o] + psum_s[3168 + o];
        }
    }
    for (int i = tid; i < 1024; i += 256) { w_s[i] = Wg[i]; w_s[1024 + i] = Wt[i]; }
    for (int i = tid; i < 4096; i += 256) w_s[2048 + i] = Wp[i];
    if (tid < 32) w_s[6144 + tid] = bg[tid] + bt[tid];
    if (tid < 128) w_s[6176 + tid] = bp[tid];
    __syncthreads();

    // ---- epilogue (lane = H column, warp owns 4 rows) ----
    const int r0 = w << 2;
    const int grow0 = (mbase + r0) * HH;
    const bool use_kp = (alpha != 0.f);

    float zi[4];
#pragma unroll
    for (int r = 0; r < 4; r++) {
        int gi = grow0 + r * HH + lane;
        float v = z[gi];
        if (use_kp) v = fmaf(alpha, kp[gi], v);
        zi[r] = v;
    }

    float bgl = w_s[6144 + lane];
    float hv[4] = {bgl, bgl, bgl, bgl};
#pragma unroll
    for (int cc2 = 0; cc2 < 32; cc2++) {
        float wg = w_s[cc2 * HH + lane];
        float wt = w_s[1024 + cc2 * HH + lane];
#pragma unroll
        for (int r = 0; r < 4; r++) {
            hv[r] = fmaf(zn_s[(r0 + r) * 33 + cc2], wg, hv[r]);
            hv[r] = fmaf(__shfl_sync(0xffffffffu, zi[r], cc2), wt, hv[r]);
        }
    }
#pragma unroll
    for (int r = 0; r < 4; r++) hv[r] = fmaxf(hv[r], 0.f);

    float4 dxr[4];
#pragma unroll
    for (int r = 0; r < 4; r++)
        dxr[r] = *reinterpret_cast<const float4*>(dx + (mbase + r0 + r) * II);
    float4 bp4 = *reinterpret_cast<const float4*>(w_s + 6176 + lane * 4);
    float kv[4];
#pragma unroll
    for (int r = 0; r < 4; r++)
        kv[r] = bp4.x * dxr[r].x + bp4.y * dxr[r].y + bp4.z * dxr[r].z + bp4.w * dxr[r].w;
#pragma unroll
    for (int j = 0; j < 32; j++) {
        float4 wp = *reinterpret_cast<const float4*>(w_s + 2048 + j * (HH * II) + lane * 4);
#pragma unroll
        for (int r = 0; r < 4; r++) {
            float t = wp.x * dxr[r].x + wp.y * dxr[r].y + wp.z * dxr[r].z + wp.w * dxr[r].w;
            kv[r] = fmaf(__shfl_sync(0xffffffffu, hv[r], j), t, kv[r]);
        }
    }

    // ---- outputs + next-stage zin (fp32 + packed bf16 transpose) ----
    float vnext[4];
    if (znext == nullptr) {
#pragma unroll
        for (int r = 0; r < 4; r++) {
            int gi = grow0 + r * HH + lane;
            kout[gi] = kv[r];
            vnext[r] = z[gi] + beta * kv[r];
        }
    } else {
#pragma unroll
        for (int r = 0; r < 4; r++) {
            int gi = grow0 + r * HH + lane;
            float zn = z[gi] + (k1[gi] + 2.f * k2[gi] + 2.f * k3[gi] + kv[r]) * (1.f / 6.f);
            znext[gi] = zn;
            vnext[r] = zn;
        }
    }

    // stage the packed bf16 transpose through smem (reuses psum_s, free now)
    unsigned short* st = reinterpret_cast<unsigned short*>(psum_s);
#pragma unroll
    for (int r = 0; r < 4; r++) {
        unsigned short hh, ll;
        bf16split(vnext[r], hh, ll);
        int stu = (lane * 8 + w) * 8 + r;
        st[stu] = hh;
        st[stu + 4] = ll;
    }
    __syncthreads();
    {
        uint4 val = reinterpret_cast<uint4*>(psum_s)[tid];
        zTw[(size_t)(tid >> 3) * 1024 + (mbase >> 2) + (tid & 7)] = val;
    }
}

// ---------------------------------------------------------------------------
// Kernel 4: decoder
// ---------------------------------------------------------------------------
__global__ __launch_bounds__(256) void decode_kernel(const float* __restrict__ zs,
                                                     const float* __restrict__ W1,
                                                     const float* __restrict__ b1,
                                                     const float* __restrict__ W2,
                                                     const float* __restrict__ b2,
                                                     float* __restrict__ out) {
    __shared__ float sW1[HH * 16];
    __shared__ float sb1[16];
    __shared__ float sW2[16];
    __shared__ float sb2;
    int tid = threadIdx.x;
    for (int i = tid; i < HH * 16; i += 256) sW1[i] = W1[i];
    if (tid < 16) { sb1[tid] = b1[tid]; sW2[tid] = W2[tid]; }
    if (tid == 0) sb2 = b2[0];
    __syncthreads();

    int r = blockIdx.x * blockDim.x + tid;
    if (r >= TT * NN) return;
    const float* zrow = zs + (size_t)r * HH;
    float zv[HH];
#pragma unroll
    for (int i = 0; i < HH; i += 4) {
        float4 v = *reinterpret_cast<const float4*>(zrow + i);
        zv[i] = v.x; zv[i + 1] = v.y; zv[i + 2] = v.z; zv[i + 3] = v.w;
    }
    float o = sb2;
#pragma unroll
    for (int j = 0; j < 16; j++) {
        float hd = sb1[j];
#pragma unroll
        for (int c2 = 0; c2 < HH; c2++) hd = fmaf(zv[c2], sW1[c2 * 16 + j], hd);
        hd = fmaxf(hd, 0.f);
        o = fmaf(hd, sW2[j], o);
    }
    out[r] = 1.f / (1.f + expf(-o));
}

// ---------------------------------------------------------------------------
// Host launcher (graph-capturable)
// ---------------------------------------------------------------------------
extern "C" void kernel_launch(void* const* d_in, const int* in_sizes, int n_in,
                              void* d_out, int out_size) {
    const float* x   = (const float*)d_in[0];
    const float* adj = (const float*)d_in[1];
    const float* We  = (const float*)d_in[2];
    const float* be  = (const float*)d_in[3];
    const float* Wg  = (const float*)d_in[4];
    const float* bg  = (const float*)d_in[5];
    const float* Wt  = (const float*)d_in[6];
    const float* bt  = (const float*)d_in[7];
    const float* Wp  = (const float*)d_in[8];
    const float* bp  = (const float*)d_in[9];
    const float* W1  = (const float*)d_in[10];
    const float* b1  = (const float*)d_in[11];
    const float* W2  = (const float*)d_in[12];
    const float* b2  = (const float*)d_in[13];
    float* out = (float*)d_out;

    float *zs, *kb, *dxb;
    uint4 *adjP, *zT;
    cudaGetSymbolAddress((void**)&zs, g_zs);
    cudaGetSymbolAddress((void**)&kb, g_k);
    cudaGetSymbolAddress((void**)&dxb, g_dx);
    cudaGetSymbolAddress((void**)&adjP, g_adjP);
    cudaGetSymbolAddress((void**)&zT, g_zT);
    uint4* zTbuf[2] = {zT, zT + HH * 1024};

    conv_adj<<<NN * 1024 / 256, 256>>>(adj, adjP);
    spline_kernel<<<CC / 256, 256>>>(x, dxb);
    z0_kernel<<<NH / 256, 256>>>(x, We, be, zs, (unsigned short*)zTbuf[0]);

    int pi = 0;
    for (int t = 0; t < 15; t++) {
        const float* zcur = zs + (size_t)t * NH;
        float* zn = zs + (size_t)(t + 1) * NH;
        float* k1 = kb;
        float* k2 = kb + NH;
        float* k3 = kb + 2 * NH;
        const float* dx0 = dxb + (0 * 15 + t) * CC;
        const float* dxh = dxb + (1 * 15 + t) * CC;
        const float* dx1 = dxb + (2 * 15 + t) * CC;

        stage_kernel<<<NN / BM, 256>>>(adjP, zTbuf[pi], zTbuf[pi ^ 1],
                                       zcur, zcur, 0.0f, 0.5f, dx0, k1,
                                       nullptr, nullptr, nullptr, nullptr,
                                       Wg, bg, Wt, bt, Wp, bp);
        pi ^= 1;
        stage_kernel<<<NN / BM, 256>>>(adjP, zTbuf[pi], zTbuf[pi ^ 1],
                                       zcur, k1, 0.5f, 0.5f, dxh, k2,
                                       nullptr, nullptr, nullptr, nullptr,
                                       Wg, bg, Wt, bt, Wp, bp);
        pi ^= 1;
        stage_kernel<<<NN / BM, 256>>>(adjP, zTbuf[pi], zTbuf[pi ^ 1],
                                       zcur, k2, 0.5f, 1.0f, dxh, k3,
                                       nullptr, nullptr, nullptr, nullptr,
                                       Wg, bg, Wt, bt, Wp, bp);
        pi ^= 1;
        stage_kernel<<<NN / BM, 256>>>(adjP, zTbuf[pi], zTbuf[pi ^ 1],
                                       zcur, k3, 1.0f, 0.0f, dx1, k1 /*unused*/,
                                       k1, k2, k3, zn,
                                       Wg, bg, Wt, bt, Wp, bp);
        pi ^= 1;
    }

    decode_kernel<<<(TT * NN) / 256, 256>>>(zs, W1, b1, W2, b2, out);
}